// round 2
// baseline (speedup 1.0000x reference)
#include <cuda_runtime.h>

// Inputs (metadata order):
//   d_in[0] = q                float32 [50000, 64]  (unused — scores cancel)
//   d_in[1] = k                float32 [50000, 64]  (unused)
//   d_in[2] = v                float32 [50000, 64]
//   d_in[3] = self_indices     int32   [800000]
//   d_in[4] = neighbor_indices int32   [800000]     (unused)
// Output: float32 [50000, 64]
//
// Math: out[n] = v[n] * sum_{e: self=n} attn_e, and the per-segment attn sum
// is exactly (sum ex)/(sum ex) = 1 for non-empty segments, 0 for empty ones.
// So out[n] = v[n] * has_incoming_edge(n).
//
// Single persistent kernel (one resident wave), software grid barriers
// between the three phases to kill the ~4us-per-launch graph-node overhead.

#define N_NODES 50000
#define N_EDGES 800000
#define D 64
#define NBLOCKS 592   // 4 blocks/SM * 148 SMs -> guaranteed single resident wave
#define NTHREADS 256

__device__ int g_flags[N_NODES];
__device__ unsigned int g_bar_count = 0;
__device__ volatile unsigned int g_bar_gen = 0;

__device__ __forceinline__ void grid_barrier() {
    __syncthreads();
    if (threadIdx.x == 0) {
        __threadfence();                       // release phase-N writes
        unsigned int gen = g_bar_gen;
        if (atomicAdd(&g_bar_count, 1u) == NBLOCKS - 1) {
            g_bar_count = 0;                   // reset BEFORE gen bump
            __threadfence();
            g_bar_gen = gen + 1;               // release
        } else {
            while (g_bar_gen == gen) { }       // L2 spin
        }
        __threadfence();                       // acquire
    }
    __syncthreads();
}

__global__ void __launch_bounds__(NTHREADS, 4) fused_kernel(
    const int* __restrict__ self_indices,
    const float4* __restrict__ v4,
    float4* __restrict__ out4)
{
    const int tid = blockIdx.x * NTHREADS + threadIdx.x;
    const int nth = NBLOCKS * NTHREADS;        // 151552 threads

    // ── Phase 1: zero flags (200 KB) ──
    for (int i = tid; i < N_NODES; i += nth)
        g_flags[i] = 0;

    grid_barrier();

    // ── Phase 2: mark nodes that appear in self_indices (3.2 MB read) ──
    for (int i = tid; i < N_EDGES; i += nth)
        g_flags[self_indices[i]] = 1;          // duplicate stores OK, no atomic

    grid_barrier();

    // ── Phase 3: gather: out = flag ? v : 0  (12.8 MB read + 12.8 MB write) ──
    const int total = N_NODES * (D / 4);       // 800000 float4
    for (int i = tid; i < total; i += nth) {
        int node = i >> 4;                     // D/4 == 16 float4 per node
        float4 val = make_float4(0.f, 0.f, 0.f, 0.f);
        if (g_flags[node]) val = v4[i];
        out4[i] = val;
    }
}

extern "C" void kernel_launch(void* const* d_in, const int* in_sizes, int n_in,
                              void* d_out, int out_size) {
    const float* v = (const float*)d_in[2];
    const int* self_indices = (const int*)d_in[3];

    fused_kernel<<<NBLOCKS, NTHREADS>>>(self_indices,
                                        (const float4*)v,
                                        (float4*)d_out);
}

// round 3
// speedup vs baseline: 1.1041x; 1.1041x over previous
#include <cuda_runtime.h>

// Inputs (metadata order):
//   d_in[0] = q                float32 [50000, 64]  (unused — scores cancel)
//   d_in[1] = k                float32 [50000, 64]  (unused)
//   d_in[2] = v                float32 [50000, 64]
//   d_in[3] = self_indices     int32   [800000]
//   d_in[4] = neighbor_indices int32   [800000]     (unused)
// Output: float32 [50000, 64]
//
// Math: out[n] = v[n] * sum_{e: self=n} attn_e; the per-segment attn sum is
// exactly (sum ex)/(sum ex) = 1 for non-empty segments and contributes 0 for
// empty ones. So out[n] = v[n] * has_incoming_edge(n).
//
// Two kernels, no grid barrier. The flag array's all-zero invariant is
// maintained by the gather kernel itself (reads flag, then resets it to 0),
// so no separate zeroing launch is needed. __device__ globals start zeroed
// at module load, and every call restores the invariant -> deterministic
// and CUDA-graph-replay safe.

#define N_NODES 50000
#define N_EDGES 800000
#define D 64

__device__ unsigned char g_flags[N_NODES];   // 50 KB, L2-resident

// K1: mark nodes appearing in self_indices. int4-vectorized index reads
// (800000 % 4 == 0), scattered byte stores (duplicates OK, no atomics).
__global__ void mark_kernel(const int4* __restrict__ self4) {
    int i = blockIdx.x * blockDim.x + threadIdx.x;
    if (i < N_EDGES / 4) {
        int4 e = self4[i];
        g_flags[e.x] = 1;
        g_flags[e.y] = 1;
        g_flags[e.z] = 1;
        g_flags[e.w] = 1;
    }
}

// K2: out = flag ? v : 0 (float4-coalesced), and reset flag to 0.
// 16 consecutive threads share one node -> flag load is a broadcast sector;
// the reset is one byte per node written by the (i%16==0) lane (~50 KB total).
__global__ void gather_kernel(const float4* __restrict__ v4,
                              float4* __restrict__ out4) {
    int i = blockIdx.x * blockDim.x + threadIdx.x;
    if (i < N_NODES * (D / 4)) {
        int node = i >> 4;                       // D/4 == 16 float4 per node
        unsigned char f = g_flags[node];
        float4 val = make_float4(0.f, 0.f, 0.f, 0.f);
        if (f) val = v4[i];
        out4[i] = val;
        if ((i & 15) == 0) g_flags[node] = 0;    // restore invariant
    }
}

extern "C" void kernel_launch(void* const* d_in, const int* in_sizes, int n_in,
                              void* d_out, int out_size) {
    const float* v = (const float*)d_in[2];
    const int* self_indices = (const int*)d_in[3];

    mark_kernel<<<(N_EDGES / 4 + 255) / 256, 256>>>((const int4*)self_indices);
    gather_kernel<<<(N_NODES * (D / 4) + 255) / 256, 256>>>(
        (const float4*)v, (float4*)d_out);
}